// round 4
// baseline (speedup 1.0000x reference)
#include <cuda_runtime.h>
#include <cuda_bf16.h>

// bow_labeler: masked mean-pool over L, then 14 small linear heads (54 outputs).
// B=256, L=512, D=768.
// Single fused kernel: grid (B, SPLIT). Each block computes a masked partial
// column-sum for a 64-row L-chunk (BW-bound stream). The last-arriving block
// per batch (fence+counter) reduces the 8 partials and runs the 54-head GEMV,
// overlapping the epilogue with remaining streaming work.

#define B_DIM   256
#define L_DIM   512
#define D_DIM   768
#define N_OUT   54
#define SPLIT   8
#define L_CHUNK (L_DIM / SPLIT)   // 64
#define D4      (D_DIM / 4)       // 192 float4 per row
#define T1      192               // one thread per float4 column
#define NWARP   (T1 / 32)         // 6

// Scratch: partial sums [B][SPLIT][D] (6 MB) + per-batch counters.
// Counters start 0 (static init) and are reset by the unique last block, so
// every graph replay sees a clean state.
__device__ float g_partial[B_DIM * SPLIT * D_DIM];
__device__ int   g_done[B_DIM];
__device__ int   g_cnt[B_DIM];

__device__ __forceinline__ void f4acc(float4& a, const float4& v) {
    a.x += v.x; a.y += v.y; a.z += v.z; a.w += v.w;
}

__global__ __launch_bounds__(T1) void bow_fused_kernel(
    const float* __restrict__ fh,
    const int*   __restrict__ mask,
    const float* __restrict__ W13,
    const float* __restrict__ b13,
    const float* __restrict__ W14,
    const float* __restrict__ b14,
    float*       __restrict__ out)
{
    const int b    = blockIdx.x;
    const int s    = blockIdx.y;
    const int tid  = threadIdx.x;      // 0..191, also the float4 column
    const int lane = tid & 31;
    const int warp = tid >> 5;

    __shared__ int    s_mask[L_CHUNK];
    __shared__ int    s_last;
    __shared__ float4 s_pooled[D4];
    __shared__ float  s_inv;

    if (tid < L_CHUNK) s_mask[tid] = mask[b * L_DIM + s * L_CHUNK + tid];
    __syncthreads();

    // Warp 0 contributes this chunk's valid-token count to g_cnt[b].
    if (warp == 0) {
        int m = s_mask[lane] + s_mask[lane + 32];
        #pragma unroll
        for (int off = 16; off; off >>= 1)
            m += __shfl_down_sync(0xffffffffu, m, off);
        if (lane == 0) atomicAdd(&g_cnt[b], m);
    }

    // Masked column sums over 64 rows: thread owns float4 column tid.
    // 8 guarded independent 16B loads per iteration keep MLP high; rows with
    // mask==0 are skipped entirely (no DRAM traffic for them).
    const float4* base =
        (const float4*)(fh + ((size_t)b * L_DIM + (size_t)s * L_CHUNK) * D_DIM) + tid;
    float4 a0 = make_float4(0.f,0.f,0.f,0.f);
    float4 a1 = make_float4(0.f,0.f,0.f,0.f);
    float4 a2 = make_float4(0.f,0.f,0.f,0.f);
    float4 a3 = make_float4(0.f,0.f,0.f,0.f);
    #pragma unroll 1
    for (int l = 0; l < L_CHUNK; l += 8) {
        if (s_mask[l+0]) f4acc(a0, base[(size_t)(l+0) * D4]);
        if (s_mask[l+1]) f4acc(a1, base[(size_t)(l+1) * D4]);
        if (s_mask[l+2]) f4acc(a2, base[(size_t)(l+2) * D4]);
        if (s_mask[l+3]) f4acc(a3, base[(size_t)(l+3) * D4]);
        if (s_mask[l+4]) f4acc(a0, base[(size_t)(l+4) * D4]);
        if (s_mask[l+5]) f4acc(a1, base[(size_t)(l+5) * D4]);
        if (s_mask[l+6]) f4acc(a2, base[(size_t)(l+6) * D4]);
        if (s_mask[l+7]) f4acc(a3, base[(size_t)(l+7) * D4]);
    }
    f4acc(a0, a1); f4acc(a2, a3); f4acc(a0, a2);

    ((float4*)(g_partial + ((size_t)b * SPLIT + s) * D_DIM))[tid] = a0;

    // Publish: make this block's stores (and its g_cnt add) visible
    // device-wide, then bump the per-batch arrival counter.
    __threadfence();
    __syncthreads();
    if (tid == 0) {
        int old = atomicAdd(&g_done[b], 1);
        s_last = (old == SPLIT - 1);
    }
    __syncthreads();
    if (!s_last) return;

    // ---- Last block for batch b: reduce partials + heads epilogue ----
    __threadfence();  // acquire: order partial reads after the counter RMW

    if (tid == 0) {
        int cnt = atomicAdd(&g_cnt[b], 0);
        s_inv = 1.0f / (float)cnt;
        g_done[b] = 0;   // reset for next launch (graph replay)
        g_cnt[b]  = 0;
    }

    const float4* gp4 = (const float4*)(g_partial + (size_t)b * SPLIT * D_DIM);
    float4 cs = make_float4(0.f,0.f,0.f,0.f);
    #pragma unroll
    for (int s2 = 0; s2 < SPLIT; s2++)
        f4acc(cs, gp4[(size_t)s2 * D4 + tid]);
    __syncthreads();
    {
        float inv = s_inv;
        cs.x *= inv; cs.y *= inv; cs.z *= inv; cs.w *= inv;
        s_pooled[tid] = cs;
    }
    __syncthreads();

    // 54 dot-products of length 768, strided over 6 warps (9 outputs each).
    for (int o = warp; o < N_OUT; o += NWARP) {
        const float4* w4 = (const float4*)((o < 52) ? (W13 + (size_t)o * D_DIM)
                                                    : (W14 + (size_t)(o - 52) * D_DIM));
        const float bias = (o < 52) ? b13[o] : b14[o - 52];
        float acc = 0.f;
        #pragma unroll
        for (int i = 0; i < D4 / 32; i++) {
            float4 w = w4[lane + 32 * i];
            float4 p = s_pooled[lane + 32 * i];
            acc += w.x * p.x + w.y * p.y + w.z * p.z + w.w * p.w;
        }
        #pragma unroll
        for (int off = 16; off; off >>= 1)
            acc += __shfl_down_sync(0xffffffffu, acc, off);
        if (lane == 0) out[b * N_OUT + o] = acc + bias;
    }
}

extern "C" void kernel_launch(void* const* d_in, const int* in_sizes, int n_in,
                              void* d_out, int out_size)
{
    const float* fh   = (const float*)d_in[0];
    const int*   mask = (const int*)d_in[1];
    const float* W13  = (const float*)d_in[2];
    const float* b13  = (const float*)d_in[3];
    const float* W14  = (const float*)d_in[4];
    const float* b14  = (const float*)d_in[5];
    float* out = (float*)d_out;

    dim3 grid(B_DIM, SPLIT);
    bow_fused_kernel<<<grid, T1>>>(fh, mask, W13, b13, W14, b14, out);
}

// round 5
// speedup vs baseline: 1.1090x; 1.1090x over previous
#include <cuda_runtime.h>
#include <cuda_bf16.h>

// bow_labeler: masked mean-pool over L, then 14 small linear heads (54 outputs).
// B=256, L=512, D=768.
// Phase 1: masked partial column sums over 64-row L-chunks (BW-bound stream).
// Phase 2: batch-tiled heads — 4 batches per block so each weight load is
//          reused 4x and the shuffle-reduce chains interleave.

#define B_DIM   256
#define L_DIM   512
#define D_DIM   768
#define N_OUT   54
#define SPLIT   8
#define L_CHUNK (L_DIM / SPLIT)   // 64
#define D4      (D_DIM / 4)       // 192 float4 per row
#define T1      192               // kernel1: one thread per float4 column
#define T2      512
#define BPB     4                 // batches per heads block
#define NB      (B_DIM / BPB)     // 64 heads blocks

// Scratch for partial sums: [B][SPLIT][D] floats = 6 MB.
__device__ float g_partial[B_DIM * SPLIT * D_DIM];

__device__ __forceinline__ void f4acc(float4& a, const float4& v) {
    a.x += v.x; a.y += v.y; a.z += v.z; a.w += v.w;
}

__global__ __launch_bounds__(T1) void pool_partial_kernel(
    const float* __restrict__ fh,
    const int*   __restrict__ mask)
{
    const int b  = blockIdx.x;
    const int s  = blockIdx.y;
    const int c4 = threadIdx.x;   // float4 column 0..191

    __shared__ int s_mask[L_CHUNK];

    if (c4 < L_CHUNK) s_mask[c4] = mask[b * L_DIM + s * L_CHUNK + c4];
    __syncthreads();

    const float4* base =
        (const float4*)(fh + ((size_t)b * L_DIM + (size_t)s * L_CHUNK) * D_DIM) + c4;

    // 64 rows per chunk; 8 guarded independent loads per unrolled body.
    float4 a0 = make_float4(0.f,0.f,0.f,0.f);
    float4 a1 = make_float4(0.f,0.f,0.f,0.f);
    float4 a2 = make_float4(0.f,0.f,0.f,0.f);
    float4 a3 = make_float4(0.f,0.f,0.f,0.f);
    #pragma unroll 1
    for (int l = 0; l < L_CHUNK; l += 8) {
        if (s_mask[l+0]) f4acc(a0, base[(size_t)(l+0) * D4]);
        if (s_mask[l+1]) f4acc(a1, base[(size_t)(l+1) * D4]);
        if (s_mask[l+2]) f4acc(a2, base[(size_t)(l+2) * D4]);
        if (s_mask[l+3]) f4acc(a3, base[(size_t)(l+3) * D4]);
        if (s_mask[l+4]) f4acc(a0, base[(size_t)(l+4) * D4]);
        if (s_mask[l+5]) f4acc(a1, base[(size_t)(l+5) * D4]);
        if (s_mask[l+6]) f4acc(a2, base[(size_t)(l+6) * D4]);
        if (s_mask[l+7]) f4acc(a3, base[(size_t)(l+7) * D4]);
    }
    f4acc(a0, a1); f4acc(a2, a3); f4acc(a0, a2);

    ((float4*)(g_partial + ((size_t)b * SPLIT + s) * D_DIM))[c4] = a0;
}

__global__ __launch_bounds__(T2) void heads_kernel(
    const int*   __restrict__ mask,
    const float* __restrict__ W13,
    const float* __restrict__ b13,
    const float* __restrict__ W14,
    const float* __restrict__ b14,
    float*       __restrict__ out)
{
    const int b0   = blockIdx.x * BPB;
    const int tid  = threadIdx.x;
    const int lane = tid & 31;
    const int warp = tid >> 5;

    __shared__ float4 s_pooled[BPB][D4];   // 12 KB
    __shared__ int    s_cnt[BPB];
    __shared__ float  s_inv[BPB];

    if (tid < BPB) s_cnt[tid] = 0;
    __syncthreads();

    // Valid-token counts for the 4 batches (512 threads, 1 mask elem each).
    #pragma unroll
    for (int bi = 0; bi < BPB; bi++) {
        int m = mask[(b0 + bi) * L_DIM + tid];
        #pragma unroll
        for (int off = 16; off; off >>= 1)
            m += __shfl_down_sync(0xffffffffu, m, off);
        if (lane == 0) atomicAdd(&s_cnt[bi], m);
    }

    // Reduce the 8 partials for each of the 768 (batch, float4-col) pairs.
    float4 cs[2];
    #pragma unroll
    for (int k = 0; k < 2; k++) {
        int idx = tid + T2 * k;
        cs[k] = make_float4(0.f,0.f,0.f,0.f);
        if (idx < BPB * D4) {
            int bi = idx / D4, c4 = idx % D4;
            const float4* gp4 =
                (const float4*)(g_partial + (size_t)(b0 + bi) * SPLIT * D_DIM);
            #pragma unroll
            for (int s = 0; s < SPLIT; s++)
                f4acc(cs[k], gp4[(size_t)s * D4 + c4]);
        }
    }

    __syncthreads();
    if (tid < BPB) s_inv[tid] = 1.0f / (float)s_cnt[tid];
    __syncthreads();

    #pragma unroll
    for (int k = 0; k < 2; k++) {
        int idx = tid + T2 * k;
        if (idx < BPB * D4) {
            int bi = idx / D4, c4 = idx % D4;
            float inv = s_inv[bi];
            float4 a = cs[k];
            a.x *= inv; a.y *= inv; a.z *= inv; a.w *= inv;
            s_pooled[bi][c4] = a;
        }
    }
    __syncthreads();

    // 54 outputs over 16 warps; weights loaded once into registers and reused
    // across the 4 batches. The 4 shuffle-reduce chains interleave for ILP.
    for (int o = warp; o < N_OUT; o += (T2 / 32)) {
        const float4* w4 = (const float4*)((o < 52) ? (W13 + (size_t)o * D_DIM)
                                                    : (W14 + (size_t)(o - 52) * D_DIM));
        const float bias = (o < 52) ? b13[o] : b14[o - 52];

        float4 w[D4 / 32];
        #pragma unroll
        for (int i = 0; i < D4 / 32; i++) w[i] = w4[lane + 32 * i];

        float acc[BPB] = {0.f, 0.f, 0.f, 0.f};
        #pragma unroll
        for (int i = 0; i < D4 / 32; i++) {
            #pragma unroll
            for (int bi = 0; bi < BPB; bi++) {
                float4 p = s_pooled[bi][lane + 32 * i];
                acc[bi] += w[i].x * p.x + w[i].y * p.y
                         + w[i].z * p.z + w[i].w * p.w;
            }
        }
        #pragma unroll
        for (int off = 16; off; off >>= 1) {
            #pragma unroll
            for (int bi = 0; bi < BPB; bi++)
                acc[bi] += __shfl_down_sync(0xffffffffu, acc[bi], off);
        }
        if (lane == 0) {
            #pragma unroll
            for (int bi = 0; bi < BPB; bi++)
                out[(b0 + bi) * N_OUT + o] = acc[bi] + bias;
        }
    }
}

extern "C" void kernel_launch(void* const* d_in, const int* in_sizes, int n_in,
                              void* d_out, int out_size)
{
    const float* fh   = (const float*)d_in[0];
    const int*   mask = (const int*)d_in[1];
    const float* W13  = (const float*)d_in[2];
    const float* b13  = (const float*)d_in[3];
    const float* W14  = (const float*)d_in[4];
    const float* b14  = (const float*)d_in[5];
    float* out = (float*)d_out;

    dim3 grid1(B_DIM, SPLIT);
    pool_partial_kernel<<<grid1, T1>>>(fh, mask);
    heads_kernel<<<NB, T2>>>(mask, W13, b13, W14, b14, out);
}

// round 6
// speedup vs baseline: 1.1651x; 1.0506x over previous
#include <cuda_runtime.h>
#include <cuda_bf16.h>

// bow_labeler: masked mean-pool over L, then 14 small linear heads (54 outputs).
// B=256, L=512, D=768.
// K1: masked partial column sums over 64-row L-chunks (BW-bound stream).
// K2: reduce 8 partials + count + normalize -> g_pooled (256 blocks).
// K3: heads GEMV, grid (64 batch-groups x 4 output-groups) = 256 blocks,
//     weights register-resident and reused across 4 batches.

#define B_DIM   256
#define L_DIM   512
#define D_DIM   768
#define N_OUT   54
#define SPLIT   8
#define L_CHUNK (L_DIM / SPLIT)   // 64
#define D4      (D_DIM / 4)       // 192 float4 per row
#define T1      192
#define T3      512
#define BPB     4                 // batches per heads block
#define NBG     (B_DIM / BPB)     // 64 batch groups
#define OGRP    4                 // output groups
#define OPG     14                // outputs per group (last group: 12)

__device__ float g_partial[B_DIM * SPLIT * D_DIM];   // 6 MB
__device__ float g_pooled[B_DIM * D_DIM];            // 0.75 MB

__device__ __forceinline__ void f4acc(float4& a, const float4& v) {
    a.x += v.x; a.y += v.y; a.z += v.z; a.w += v.w;
}

// ---------------- K1: masked partial sums ----------------
__global__ __launch_bounds__(T1) void pool_partial_kernel(
    const float* __restrict__ fh,
    const int*   __restrict__ mask)
{
    const int b  = blockIdx.x;
    const int s  = blockIdx.y;
    const int c4 = threadIdx.x;

    __shared__ int s_mask[L_CHUNK];
    if (c4 < L_CHUNK) s_mask[c4] = mask[b * L_DIM + s * L_CHUNK + c4];
    __syncthreads();

    const float4* base =
        (const float4*)(fh + ((size_t)b * L_DIM + (size_t)s * L_CHUNK) * D_DIM) + c4;

    float4 a0 = make_float4(0.f,0.f,0.f,0.f);
    float4 a1 = make_float4(0.f,0.f,0.f,0.f);
    float4 a2 = make_float4(0.f,0.f,0.f,0.f);
    float4 a3 = make_float4(0.f,0.f,0.f,0.f);
    #pragma unroll 1
    for (int l = 0; l < L_CHUNK; l += 8) {
        if (s_mask[l+0]) f4acc(a0, base[(size_t)(l+0) * D4]);
        if (s_mask[l+1]) f4acc(a1, base[(size_t)(l+1) * D4]);
        if (s_mask[l+2]) f4acc(a2, base[(size_t)(l+2) * D4]);
        if (s_mask[l+3]) f4acc(a3, base[(size_t)(l+3) * D4]);
        if (s_mask[l+4]) f4acc(a0, base[(size_t)(l+4) * D4]);
        if (s_mask[l+5]) f4acc(a1, base[(size_t)(l+5) * D4]);
        if (s_mask[l+6]) f4acc(a2, base[(size_t)(l+6) * D4]);
        if (s_mask[l+7]) f4acc(a3, base[(size_t)(l+7) * D4]);
    }
    f4acc(a0, a1); f4acc(a2, a3); f4acc(a0, a2);

    ((float4*)(g_partial + ((size_t)b * SPLIT + s) * D_DIM))[c4] = a0;
}

// ---------------- K2: reduce partials + normalize ----------------
__global__ __launch_bounds__(T1) void pool_reduce_kernel(
    const int* __restrict__ mask)
{
    const int b    = blockIdx.x;
    const int tid  = threadIdx.x;      // float4 column 0..191
    const int lane = tid & 31;

    __shared__ int   s_cnt;
    __shared__ float s_inv;

    if (tid == 0) s_cnt = 0;
    __syncthreads();

    // Count valid tokens: 192 threads cover 512 mask elems (3 loads, last partial).
    {
        const int* mrow = mask + b * L_DIM;
        int m = mrow[tid] + mrow[tid + 192] + ((tid < 128) ? mrow[tid + 384] : 0);
        #pragma unroll
        for (int off = 16; off; off >>= 1)
            m += __shfl_down_sync(0xffffffffu, m, off);
        if (lane == 0) atomicAdd(&s_cnt, m);
    }

    const float4* gp4 = (const float4*)(g_partial + (size_t)b * SPLIT * D_DIM);
    float4 cs = make_float4(0.f,0.f,0.f,0.f);
    #pragma unroll
    for (int s = 0; s < SPLIT; s++)
        f4acc(cs, gp4[(size_t)s * D4 + tid]);

    __syncthreads();
    if (tid == 0) s_inv = 1.0f / (float)s_cnt;
    __syncthreads();

    float inv = s_inv;
    cs.x *= inv; cs.y *= inv; cs.z *= inv; cs.w *= inv;
    ((float4*)(g_pooled + (size_t)b * D_DIM))[tid] = cs;
}

// ---------------- K3: heads GEMV ----------------
__global__ __launch_bounds__(T3) void heads_kernel(
    const float* __restrict__ W13,
    const float* __restrict__ b13,
    const float* __restrict__ W14,
    const float* __restrict__ b14,
    float*       __restrict__ out)
{
    const int b0   = blockIdx.x * BPB;        // batch group
    const int og   = blockIdx.y;              // output group
    const int tid  = threadIdx.x;
    const int lane = tid & 31;
    const int warp = tid >> 5;

    __shared__ float4 s_pooled[BPB][D4];      // 12 KB

    // Stage 4 pooled vectors (768 float4 total, 512 threads -> 2 loads each).
    #pragma unroll
    for (int k = 0; k < 2; k++) {
        int idx = tid + T3 * k;
        if (idx < BPB * D4) {
            int bi = idx / D4, c4 = idx % D4;
            s_pooled[bi][c4] =
                ((const float4*)(g_pooled + (size_t)(b0 + bi) * D_DIM))[c4];
        }
    }
    __syncthreads();

    // Warp w handles output og*OPG + w (for w < group size) across 4 batches.
    const int o = og * OPG + warp;
    const int o_end = min((og + 1) * OPG, N_OUT);
    if (warp >= OPG || o >= o_end) return;

    const float4* w4 = (const float4*)((o < 52) ? (W13 + (size_t)o * D_DIM)
                                                : (W14 + (size_t)(o - 52) * D_DIM));
    const float bias = (o < 52) ? b13[o] : b14[o - 52];

    float4 w[D4 / 32];
    #pragma unroll
    for (int i = 0; i < D4 / 32; i++) w[i] = w4[lane + 32 * i];

    float acc[BPB] = {0.f, 0.f, 0.f, 0.f};
    #pragma unroll
    for (int i = 0; i < D4 / 32; i++) {
        #pragma unroll
        for (int bi = 0; bi < BPB; bi++) {
            float4 p = s_pooled[bi][lane + 32 * i];
            acc[bi] += w[i].x * p.x + w[i].y * p.y + w[i].z * p.z + w[i].w * p.w;
        }
    }
    #pragma unroll
    for (int off = 16; off; off >>= 1) {
        #pragma unroll
        for (int bi = 0; bi < BPB; bi++)
            acc[bi] += __shfl_down_sync(0xffffffffu, acc[bi], off);
    }
    if (lane == 0) {
        #pragma unroll
        for (int bi = 0; bi < BPB; bi++)
            out[(b0 + bi) * N_OUT + o] = acc[bi] + bias;
    }
}

extern "C" void kernel_launch(void* const* d_in, const int* in_sizes, int n_in,
                              void* d_out, int out_size)
{
    const float* fh   = (const float*)d_in[0];
    const int*   mask = (const int*)d_in[1];
    const float* W13  = (const float*)d_in[2];
    const float* b13  = (const float*)d_in[3];
    const float* W14  = (const float*)d_in[4];
    const float* b14  = (const float*)d_in[5];
    float* out = (float*)d_out;

    dim3 grid1(B_DIM, SPLIT);
    pool_partial_kernel<<<grid1, T1>>>(fh, mask);
    pool_reduce_kernel<<<B_DIM, T1>>>(mask);
    dim3 grid3(NBG, OGRP);
    heads_kernel<<<grid3, T3>>>(W13, b13, W14, b14, out);
}